// round 11
// baseline (speedup 1.0000x reference)
#include <cuda_runtime.h>
#include <cuda_bf16.h>
#include <cuda_fp16.h>
#include <math.h>
#include <stdint.h>

#define Bb   256
#define NR   64
#define NH   8
#define Ee   512
#define TOPKK 16
#define EPSF 1e-7f

#define VSPLIT 32
#define VSUM_ELEMS (Bb * Ee)

// ---------------- device scratch ----------------
__device__ float g_qp[Bb * NR * Ee];
__device__ float g_kp[Bb * NR * Ee];
__device__ float g_vpart[VSPLIT * VSUM_ELEMS];
__device__ float g_vsum[VSUM_ELEMS];
__device__ float g_attn[Bb * NR * NH];
__device__ float g_F[Bb * NH * Ee];
__device__ float g_G[Bb * NH * Ee];

// ---------------- smem geometry for GEMM (bytes) ----------------
#define APITCH_B 80
#define BPITCH_B 272
#define APL 10240
#define BPL 8704
#define AOFF 0
#define BOFF (2 * APL)
#define BUFSZ (2 * APL + 2 * BPL)      /* 37888 */
#define GEMM_SMEM (2 * BUFSZ)          /* 75776 */

__device__ __forceinline__ uint32_t smem_u32(const void* p) {
    uint32_t a;
    asm("{ .reg .u64 t; cvta.to.shared.u64 t, %1; cvt.u32.u64 %0, t; }" : "=r"(a) : "l"(p));
    return a;
}
__device__ __forceinline__ void ldm_x4(uint32_t* r, uint32_t addr) {
    asm volatile("ldmatrix.sync.aligned.m8n8.x4.shared.b16 {%0,%1,%2,%3}, [%4];"
                 : "=r"(r[0]), "=r"(r[1]), "=r"(r[2]), "=r"(r[3]) : "r"(addr));
}
__device__ __forceinline__ void ldm_x4t(uint32_t* r, uint32_t addr) {
    asm volatile("ldmatrix.sync.aligned.m8n8.x4.trans.shared.b16 {%0,%1,%2,%3}, [%4];"
                 : "=r"(r[0]), "=r"(r[1]), "=r"(r[2]), "=r"(r[3]) : "r"(addr));
}

// packed converts: first src operand -> UPPER half (PTX cvt two-operand form)
__device__ __forceinline__ uint32_t bf2(float up, float lo) {
    uint32_t r;
    asm("cvt.rn.bf16x2.f32 %0, %1, %2;" : "=r"(r) : "f"(up), "f"(lo));
    return r;
}
__device__ __forceinline__ uint32_t hf2(float up, float lo) {
    uint32_t r;
    asm("cvt.rn.f16x2.f32 %0, %1, %2;" : "=r"(r) : "f"(up), "f"(lo));
    return r;
}

// fp32 -> (hi, mid) bf16 planes packed as uint2 (4 lanes), packed-cvt version
__device__ __forceinline__ void split2_pack(float4 v, uint2& hw, uint2& mw) {
    hw.x = bf2(v.y, v.x);
    hw.y = bf2(v.w, v.z);
    float h0 = __uint_as_float(hw.x << 16);
    float h1 = __uint_as_float(hw.x & 0xFFFF0000u);
    float h2 = __uint_as_float(hw.y << 16);
    float h3 = __uint_as_float(hw.y & 0xFFFF0000u);
    mw.x = bf2(v.y - h1, v.x - h0);
    mw.y = bf2(v.w - h3, v.z - h2);
}
// fp32 -> f16 single plane
__device__ __forceinline__ uint2 f16_pack(float4 v) {
    uint2 w;
    w.x = hf2(v.y, v.x);
    w.y = hf2(v.w, v.z);
    return w;
}

#define MMA_BF(AF, BF, mi, ni)                                                 \
    asm volatile(                                                              \
        "mma.sync.aligned.m16n8k16.row.col.f32.bf16.bf16.f32 "                 \
        "{%0,%1,%2,%3}, {%4,%5,%6,%7}, {%8,%9}, {%0,%1,%2,%3};"                \
        : "+f"(acc[mi][ni][0]), "+f"(acc[mi][ni][1]),                          \
          "+f"(acc[mi][ni][2]), "+f"(acc[mi][ni][3])                           \
        : "r"(AF[mi][0]), "r"(AF[mi][1]), "r"(AF[mi][2]), "r"(AF[mi][3]),      \
          "r"(BF[ni][0]), "r"(BF[ni][1]))
#define MMA_F16(AF, BF, mi, ni)                                                \
    asm volatile(                                                              \
        "mma.sync.aligned.m16n8k16.row.col.f32.f16.f16.f32 "                   \
        "{%0,%1,%2,%3}, {%4,%5,%6,%7}, {%8,%9}, {%0,%1,%2,%3};"                \
        : "+f"(acc[mi][ni][0]), "+f"(acc[mi][ni][1]),                          \
          "+f"(acc[mi][ni][2]), "+f"(acc[mi][ni][3])                           \
        : "r"(AF[mi][0]), "r"(AF[mi][1]), "r"(AF[mi][2]), "r"(AF[mi][3]),      \
          "r"(BF[ni][0]), "r"(BF[ni][1]))

// ---------------- mixed-precision mma.sync GEMM: C = A @ W ----------------
// BM=128 BN=128 BK=32, 256 threads (8 warps 2x4), warp tile 64x32.
// z<32: vsum split-K (f16x1, LONGEST -> dispatched FIRST);
// z in [32,96): qproj (bf16x3); z in [96,160): kproj (bf16x3).
__global__ __launch_bounds__(256) void gemm_mma(
    const float* __restrict__ q, const float* __restrict__ k,
    const float* __restrict__ v, const float* __restrict__ Wq,
    const float* __restrict__ Wk, const float* __restrict__ Wv)
{
    extern __shared__ char smc[];
    uint32_t sb = smem_u32(smc);
    int tid = threadIdx.x, lane = tid & 31, warp = tid >> 5;
    int z = blockIdx.z;
    long bm = (long)blockIdx.y * 128;
    int n0 = blockIdx.x * 128;

    const float* A; const float* W; float* C;
    long lda, ldc; int nChunks; bool np3;
    if (z < 32) {
        A = v + (long)z * 1024;
        W = Wv + (long)z * 1024 * 512;
        C = g_vpart + (long)z * VSUM_ELEMS;
        lda = 32768; ldc = 512; nChunks = 32; np3 = false;
    } else if (z < 96) {
        int g = z - 32;
        A = q + (long)g * 512; W = Wq + (long)g * 262144;
        C = g_qp + (long)g * 512; lda = 32768; ldc = 32768; nChunks = 16; np3 = true;
    } else {
        int g = z - 96;
        A = k + (long)g * 512; W = Wk + (long)g * 262144;
        C = g_kp + (long)g * 512; lda = 32768; ldc = 32768; nChunks = 16; np3 = true;
    }

    int wm0 = (warp >> 2) * 64;
    int wn0 = (warp & 3) * 32;
    int g8 = lane >> 2, tq = lane & 3;

    int lrow = ((lane >> 3) & 1) * 8 + (lane & 7);
    int lk16 = ((lane >> 4) & 1) * 16;
    uint32_t aLane = sb + AOFF + (uint32_t)(wm0 + lrow) * APITCH_B + lk16;
    uint32_t bLane = sb + BOFF + (uint32_t)lrow * BPITCH_B + (uint32_t)(wn0 + ((lane >> 4) & 1) * 8) * 2;

    int am = tid >> 3, akf = (tid & 7) * 4;
    const float* Aload = A + (bm + am) * lda + akf;

    float acc[4][4][4];
#pragma unroll
    for (int mi = 0; mi < 4; mi++)
#pragma unroll
        for (int ni = 0; ni < 4; ni++)
#pragma unroll
            for (int c = 0; c < 4; c++) acc[mi][ni][c] = 0.f;

    float4 ra[4], rb[4];

#define LOADG(kb)                                                              \
    do {                                                                       \
        _Pragma("unroll")                                                      \
        for (int i = 0; i < 4; i++) {                                          \
            ra[i] = *(const float4*)(Aload + (long)(i * 32) * lda + (kb));     \
            int lin = tid + i * 256;                                           \
            int kk = lin >> 5, nf = lin & 31;                                  \
            rb[i] = *(const float4*)(W + ((kb) + kk) * 512 + n0 + nf * 4);     \
        }                                                                      \
    } while (0)

#define STORE(buf)                                                             \
    do {                                                                       \
        char* bp = smc + (buf) * BUFSZ;                                        \
        _Pragma("unroll")                                                      \
        for (int i = 0; i < 4; i++) {                                          \
            char* ap = bp + AOFF + (am + i * 32) * APITCH_B + akf * 2;         \
            int lin = tid + i * 256;                                           \
            int kk = lin >> 5, nf = lin & 31;                                  \
            char* wp = bp + BOFF + kk * BPITCH_B + nf * 8;                     \
            if (np3) {                                                         \
                uint2 hw, mw;                                                  \
                split2_pack(ra[i], hw, mw);                                    \
                *(uint2*)ap = hw; *(uint2*)(ap + APL) = mw;                    \
                split2_pack(rb[i], hw, mw);                                    \
                *(uint2*)wp = hw; *(uint2*)(wp + BPL) = mw;                    \
            } else {                                                           \
                *(uint2*)ap = f16_pack(ra[i]);                                 \
                *(uint2*)wp = f16_pack(rb[i]);                                 \
            }                                                                  \
        }                                                                      \
    } while (0)

    LOADG(0);
    STORE(0);
    if (nChunks > 1) LOADG(32);
    __syncthreads();

    for (int kt = 0; kt < nChunks; kt++) {
        int cur = kt & 1;
        if (kt + 1 < nChunks) {
            STORE(cur ^ 1);
            if (kt + 2 < nChunks) LOADG((long)(kt + 2) * 32);
        }
        uint32_t bufOff = (uint32_t)cur * BUFSZ;
#pragma unroll
        for (int ks = 0; ks < 2; ks++) {
            uint32_t Ah[4][4], Am[4][4];
#pragma unroll
            for (int mt = 0; mt < 4; mt++) {
                uint32_t ad = aLane + bufOff + mt * (16 * APITCH_B) + ks * 32;
                ldm_x4(Ah[mt], ad);
                if (np3) ldm_x4(Am[mt], ad + APL);
            }
            uint32_t Bh[4][2], Bm[4][2];
#pragma unroll
            for (int pr = 0; pr < 2; pr++) {
                uint32_t bd = bLane + bufOff + ks * (16 * BPITCH_B) + pr * 32;
                uint32_t r4[4];
                ldm_x4t(r4, bd);
                Bh[2 * pr][0] = r4[0]; Bh[2 * pr][1] = r4[1];
                Bh[2 * pr + 1][0] = r4[2]; Bh[2 * pr + 1][1] = r4[3];
                if (np3) {
                    ldm_x4t(r4, bd + BPL);
                    Bm[2 * pr][0] = r4[0]; Bm[2 * pr][1] = r4[1];
                    Bm[2 * pr + 1][0] = r4[2]; Bm[2 * pr + 1][1] = r4[3];
                }
            }
            if (np3) {
#pragma unroll
                for (int mt = 0; mt < 4; mt++)
#pragma unroll
                    for (int nt = 0; nt < 4; nt++) {
                        MMA_BF(Am, Bh, mt, nt);
                        MMA_BF(Ah, Bm, mt, nt);
                        MMA_BF(Ah, Bh, mt, nt);
                    }
            } else {
#pragma unroll
                for (int mt = 0; mt < 4; mt++)
#pragma unroll
                    for (int nt = 0; nt < 4; nt++)
                        MMA_F16(Ah, Bh, mt, nt);
            }
        }
        __syncthreads();
    }
#undef LOADG
#undef STORE

#pragma unroll
    for (int mt = 0; mt < 4; mt++) {
        long r0 = bm + wm0 + mt * 16 + g8;
#pragma unroll
        for (int nt = 0; nt < 4; nt++) {
            long c0 = n0 + wn0 + nt * 8 + 2 * tq;
            *(float2*)(C + r0 * ldc + c0) = make_float2(acc[mt][nt][0], acc[mt][nt][1]);
            *(float2*)(C + (r0 + 8) * ldc + c0) = make_float2(acc[mt][nt][2], acc[mt][nt][3]);
        }
    }
}

// ---------------- split-K reduction for vsum (float2, 256 blocks) ----------------
__global__ __launch_bounds__(256) void reduce_vsum()
{
    int idx = (blockIdx.x * 256 + threadIdx.x) * 2;
    float2 s = make_float2(0.f, 0.f);
#pragma unroll
    for (int i = 0; i < VSPLIT; i++) {
        float2 p = *(const float2*)&g_vpart[(long)i * VSUM_ELEMS + idx];
        s.x += p.x; s.y += p.y;
    }
    *(float2*)&g_vsum[idx] = s;
}

// ---------------- attention weights (MMA-based scores) ----------------
__global__ __launch_bounds__(256) void attn_kernel()
{
    __shared__ __align__(16) unsigned short Qh[64 * 72], Qm[64 * 72];
    __shared__ __align__(16) unsigned short Kh[64 * 72], Km[64 * 72];
    __shared__ float colmax[2][64];
    __shared__ float ev[64], av[64], wv[64];
    __shared__ float red[2], red2[2];
    __shared__ int cntS[4][64];
    __shared__ float dsh;
    int h = blockIdx.x, b = blockIdx.y;
    int t = threadIdx.x, lane = t & 31, w = t >> 5;

    const float* qpB = g_qp + (long)b * 64 * 512 + h * 64;
    const float* kpB = g_kp + (long)b * 64 * 512 + h * 64;
#pragma unroll
    for (int i = 0; i < 4; i++) {
        int idx = t + i * 256;
        int r = idx >> 4, c4 = (idx & 15) * 4;
        float4 qv = *(const float4*)(qpB + (long)r * 512 + c4);
        float4 kv = *(const float4*)(kpB + (long)r * 512 + c4);
        uint2 hw, mw;
        split2_pack(qv, hw, mw);
        *(uint2*)&Qh[r * 72 + c4] = hw;
        *(uint2*)&Qm[r * 72 + c4] = mw;
        split2_pack(kv, hw, mw);
        *(uint2*)&Kh[r * 72 + c4] = hw;
        *(uint2*)&Km[r * 72 + c4] = mw;
    }
    __syncthreads();

    int wr = w & 3, wc = w >> 2;
    int r0 = wr * 16, n0 = wc * 32;
    int am_row = r0 + ((lane >> 3) & 1) * 8 + (lane & 7);
    int am_col = (lane >> 4) * 16;
    uint32_t aQh = smem_u32(Qh) + am_row * 144 + am_col;
    uint32_t aQm = smem_u32(Qm) + am_row * 144 + am_col;
    int sel = (lane >> 3) & 3;
    int brow = (sel >> 1) * 8 + (lane & 7);
    int bcol = (sel & 1) * 16;
    uint32_t aKh = smem_u32(Kh) + bcol;
    uint32_t aKm = smem_u32(Km) + bcol;

    float acc[4][4];
#pragma unroll
    for (int i = 0; i < 4; i++)
#pragma unroll
        for (int j = 0; j < 4; j++) acc[i][j] = 0.f;

#pragma unroll
    for (int ks = 0; ks < 4; ks++) {
        uint32_t Ah[4], Am[4];
        ldm_x4(Ah, aQh + ks * 32);
        ldm_x4(Am, aQm + ks * 32);
#pragma unroll
        for (int ntp = 0; ntp < 2; ntp++) {
            uint32_t off = (uint32_t)(n0 + ntp * 16 + brow) * 144 + ks * 32;
            uint32_t r4[4];
            uint32_t Bh[2][2], Bm[2][2];
            ldm_x4(r4, aKh + off);
            Bh[0][0] = r4[0]; Bh[0][1] = r4[1]; Bh[1][0] = r4[2]; Bh[1][1] = r4[3];
            ldm_x4(r4, aKm + off);
            Bm[0][0] = r4[0]; Bm[0][1] = r4[1]; Bm[1][0] = r4[2]; Bm[1][1] = r4[3];
#pragma unroll
            for (int j = 0; j < 2; j++) {
                int nt = ntp * 2 + j;
                asm volatile(
                    "mma.sync.aligned.m16n8k16.row.col.f32.bf16.bf16.f32 "
                    "{%0,%1,%2,%3}, {%4,%5,%6,%7}, {%8,%9}, {%0,%1,%2,%3};"
                    : "+f"(acc[nt][0]), "+f"(acc[nt][1]), "+f"(acc[nt][2]), "+f"(acc[nt][3])
                    : "r"(Am[0]), "r"(Am[1]), "r"(Am[2]), "r"(Am[3]),
                      "r"(Bh[j][0]), "r"(Bh[j][1]));
                asm volatile(
                    "mma.sync.aligned.m16n8k16.row.col.f32.bf16.bf16.f32 "
                    "{%0,%1,%2,%3}, {%4,%5,%6,%7}, {%8,%9}, {%0,%1,%2,%3};"
                    : "+f"(acc[nt][0]), "+f"(acc[nt][1]), "+f"(acc[nt][2]), "+f"(acc[nt][3])
                    : "r"(Ah[0]), "r"(Ah[1]), "r"(Ah[2]), "r"(Ah[3]),
                      "r"(Bm[j][0]), "r"(Bm[j][1]));
                asm volatile(
                    "mma.sync.aligned.m16n8k16.row.col.f32.bf16.bf16.f32 "
                    "{%0,%1,%2,%3}, {%4,%5,%6,%7}, {%8,%9}, {%0,%1,%2,%3};"
                    : "+f"(acc[nt][0]), "+f"(acc[nt][1]), "+f"(acc[nt][2]), "+f"(acc[nt][3])
                    : "r"(Ah[0]), "r"(Ah[1]), "r"(Ah[2]), "r"(Ah[3]),
                      "r"(Bh[j][0]), "r"(Bh[j][1]));
            }
        }
    }

    float m1 = acc[0][0], m2 = acc[0][2];
#pragma unroll
    for (int nt = 0; nt < 4; nt++) {
        m1 = fmaxf(m1, fmaxf(acc[nt][0], acc[nt][1]));
        m2 = fmaxf(m2, fmaxf(acc[nt][2], acc[nt][3]));
    }
    m1 = fmaxf(m1, __shfl_xor_sync(0xffffffffu, m1, 1));
    m1 = fmaxf(m1, __shfl_xor_sync(0xffffffffu, m1, 2));
    m2 = fmaxf(m2, __shfl_xor_sync(0xffffffffu, m2, 1));
    m2 = fmaxf(m2, __shfl_xor_sync(0xffffffffu, m2, 2));
    if ((lane & 3) == 0) {
        colmax[wc][r0 + (lane >> 2)] = m1;
        colmax[wc][r0 + (lane >> 2) + 8] = m2;
    }
    __syncthreads();
    if (t < 64) ev[t] = expf(fmaxf(colmax[0][t], colmax[1][t]) * 0.125f);
    __syncthreads();

    if (t < 64) {
        float m = ev[t];
#pragma unroll
        for (int s = 16; s > 0; s >>= 1) m = fmaxf(m, __shfl_xor_sync(0xffffffffu, m, s));
        if (lane == 0) red[w] = m;
    }
    __syncthreads();
    if (t < 64) {
        float m = fmaxf(red[0], red[1]);
        float sx = expf(ev[t] - m);
        av[t] = sx;
        float ss = sx;
#pragma unroll
        for (int s = 16; s > 0; s >>= 1) ss += __shfl_xor_sync(0xffffffffu, ss, s);
        if (lane == 0) red2[w] = ss;
    }
    __syncthreads();
    if (t < 64) av[t] = av[t] / (red2[0] + red2[1]);
    __syncthreads();

    {
        int r = t & 63, part = t >> 6;
        float ar = av[r];
        int cnt = 0;
        int j0 = part * 16;
#pragma unroll
        for (int j = 0; j < 16; j++) {
            float o = av[j0 + j];
            cnt += (o > ar) || (o == ar && (j0 + j) < r);
        }
        cntS[part][r] = cnt;
    }
    __syncthreads();
    if (t < 64) {
        int cnt = cntS[0][t] + cntS[1][t] + cntS[2][t] + cntS[3][t];
        if (cnt == TOPKK - 1) dsh = av[t];
    }
    __syncthreads();
    if (t < 64) {
        float wq = fmaxf(av[t] - (dsh + EPSF), 0.f);
        wv[t] = wq;
        float ws = wq;
#pragma unroll
        for (int s = 16; s > 0; s >>= 1) ws += __shfl_xor_sync(0xffffffffu, ws, s);
        if (lane == 0) red[w] = ws;
    }
    __syncthreads();
    if (t < 64)
        g_attn[((long)b * 64 + t) * 8 + h] = wv[t] / (red[0] + red[1] + EPSF);
}

// ---------------- F/G via f16 mma: per head (256b x 64d) @ W_h^T (64d x 512o) ----------------
// grid (NH, 2 m-tiles of 128 b, 8 n-tiles: z<4 -> F cols z*128, z>=4 -> G cols (z-4)*128)
#define FG_AP 144
#define FG_BP 144
__global__ __launch_bounds__(256) void fg_mma(const float* __restrict__ fc_w,
                                              const float* __restrict__ gate_w)
{
    __shared__ __align__(16) char As[128 * FG_AP];   /* 18432 */
    __shared__ __align__(16) char Bs[128 * FG_BP];   /* 18432 */
    int h = blockIdx.x;
    int b0 = blockIdx.y * 128;
    int zn = blockIdx.z;
    const float* Wsel = (zn < 4) ? fc_w : gate_w;
    float* Out = (zn < 4) ? g_F : g_G;
    int o0 = (zn & 3) * 128;
    int tid = threadIdx.x, lane = tid & 31, warp = tid >> 5;

#pragma unroll
    for (int i = 0; i < 8; i++) {
        int lin = tid + i * 256;
        int r = lin >> 4, c4 = (lin & 15) * 4;
        float4 av = *(const float4*)&g_vsum[(long)(b0 + r) * 512 + h * 64 + c4];
        *(uint2*)(As + r * FG_AP + c4 * 2) = f16_pack(av);
        float4 bv = *(const float4*)&Wsel[(long)(o0 + r) * 512 + h * 64 + c4];
        *(uint2*)(Bs + r * FG_BP + c4 * 2) = f16_pack(bv);
    }
    __syncthreads();

    int wm0 = (warp >> 2) * 64, wn0 = (warp & 3) * 32;
    int g8 = lane >> 2, tq = lane & 3;
    int arow = ((lane >> 3) & 1) * 8 + (lane & 7);
    int acol = (lane >> 4) * 16;
    uint32_t aBase = smem_u32(As) + (uint32_t)(wm0 + arow) * FG_AP + acol;
    int sel = (lane >> 3) & 3;
    int brow = (sel >> 1) * 8 + (lane & 7);
    int bcol = (sel & 1) * 16;
    uint32_t bBase = smem_u32(Bs) + bcol;

    float acc[4][4][4];
#pragma unroll
    for (int mi = 0; mi < 4; mi++)
#pragma unroll
        for (int ni = 0; ni < 4; ni++)
#pragma unroll
            for (int c = 0; c < 4; c++) acc[mi][ni][c] = 0.f;

#pragma unroll
    for (int ks = 0; ks < 4; ks++) {
        uint32_t Af[4][4];
#pragma unroll
        for (int mt = 0; mt < 4; mt++)
            ldm_x4(Af[mt], aBase + mt * (16 * FG_AP) + ks * 32);
        uint32_t Bf[4][2];
#pragma unroll
        for (int ntp = 0; ntp < 2; ntp++) {
            uint32_t r4[4];
            ldm_x4(r4, bBase + (uint32_t)(wn0 + ntp * 16 + brow) * FG_BP + ks * 32);
            Bf[2 * ntp][0] = r4[0]; Bf[2 * ntp][1] = r4[1];
            Bf[2 * ntp + 1][0] = r4[2]; Bf[2 * ntp + 1][1] = r4[3];
        }
#pragma unroll
        for (int mt = 0; mt < 4; mt++)
#pragma unroll
            for (int nt = 0; nt < 4; nt++)
                MMA_F16(Af, Bf, mt, nt);
    }

#pragma unroll
    for (int mt = 0; mt < 4; mt++) {
        int br = b0 + wm0 + mt * 16 + g8;
#pragma unroll
        for (int nt = 0; nt < 4; nt++) {
            int col = o0 + wn0 + nt * 8 + 2 * tq;
            *(float2*)&Out[((long)br * 8 + h) * 512 + col] =
                make_float2(acc[mt][nt][0], acc[mt][nt][1]);
            *(float2*)&Out[((long)(br + 8) * 8 + h) * 512 + col] =
                make_float2(acc[mt][nt][2], acc[mt][nt][3]);
        }
    }
}

// ---------------- final gated combine ----------------
__global__ __launch_bounds__(256) void final_kernel(const float* __restrict__ fc_b,
                                                    const float* __restrict__ gate_b,
                                                    float* __restrict__ out)
{
    __shared__ float aw[64][8];
    __shared__ float Fs[8][128];
    __shared__ float Gs[8][128];
    __shared__ float fb[128], gb[128];
    int o0 = blockIdx.x * 128;
    int b = blockIdx.y;
    int t = threadIdx.x;

    for (int i = t; i < 512; i += 256)
        ((float*)aw)[i] = g_attn[(long)b * 512 + i];
    for (int i = t; i < 1024; i += 256) {
        int h = i >> 7, o = i & 127;
        Fs[h][o] = g_F[((long)b * 8 + h) * 512 + o0 + o];
        Gs[h][o] = g_G[((long)b * 8 + h) * 512 + o0 + o];
    }
    if (t < 128) {
        fb[t] = fc_b[o0 + t];
        gb[t] = gate_b[o0 + t];
    }
    __syncthreads();

    int oc = t & 31, rw = t >> 5;
    for (int r = rw; r < 64; r += 8) {
        float ah[8];
#pragma unroll
        for (int h = 0; h < 8; h++) ah[h] = aw[r][h];
        for (int ob = 0; ob < 128; ob += 32) {
            int o = ob + oc;
            float f = fb[o], g = gb[o];
#pragma unroll
            for (int h = 0; h < 8; h++) {
                f = fmaf(ah[h], Fs[h][o], f);
                g = fmaf(ah[h], Gs[h][o], g);
            }
            float sg = 1.f / (1.f + expf(-g));
            out[((long)b * 64 + r) * 512 + o0 + o] = sg * tanhf(f);
        }
    }
}

// ---------------- launch ----------------
extern "C" void kernel_launch(void* const* d_in, const int* in_sizes, int n_in,
                              void* d_out, int out_size)
{
    const float* q      = (const float*)d_in[0];
    const float* k      = (const float*)d_in[1];
    const float* v      = (const float*)d_in[2];
    const float* Wq     = (const float*)d_in[3];
    const float* Wk     = (const float*)d_in[4];
    const float* Wv     = (const float*)d_in[5];
    const float* fc_w   = (const float*)d_in[6];
    const float* fc_b   = (const float*)d_in[7];
    const float* gate_w = (const float*)d_in[8];
    const float* gate_b = (const float*)d_in[9];
    float* out = (float*)d_out;
    (void)in_sizes; (void)n_in; (void)out_size;

    cudaFuncSetAttribute(gemm_mma, cudaFuncAttributeMaxDynamicSharedMemorySize,
                         GEMM_SMEM);

    // z<32 vsum split-K (longest, dispatched first), z<96 qproj, z<160 kproj
    gemm_mma<<<dim3(4, 2, 160), 256, GEMM_SMEM>>>(q, k, v, Wq, Wk, Wv);
    reduce_vsum<<<VSUM_ELEMS / 512, 256>>>();

    attn_kernel<<<dim3(NH, Bb), 256>>>();
    fg_mma<<<dim3(NH, 2, 8), 256>>>(fc_w, gate_w);
    final_kernel<<<dim3(4, Bb), 256>>>(fc_b, gate_b, out);
}

// round 12
// speedup vs baseline: 1.0261x; 1.0261x over previous
#include <cuda_runtime.h>
#include <cuda_bf16.h>
#include <cuda_fp16.h>
#include <math.h>
#include <stdint.h>

#define Bb   256
#define NR   64
#define NH   8
#define Ee   512
#define TOPKK 16
#define EPSF 1e-7f

#define VSPLIT 32
#define VSUM_ELEMS (Bb * Ee)

// ---------------- device scratch ----------------
__device__ float g_qp[Bb * NR * Ee];
__device__ float g_kp[Bb * NR * Ee];
__device__ float g_vpart[VSPLIT * VSUM_ELEMS];
__device__ float g_vsum[VSUM_ELEMS];
__device__ float g_attn[Bb * NR * NH];
__device__ float g_F[Bb * NH * Ee];
__device__ float g_G[Bb * NH * Ee];

// ---------------- smem geometry for GEMM (bytes) ----------------
#define APITCH_B 80
#define BPITCH_B 272
#define APL 10240
#define BPL 8704
#define AOFF 0
#define BOFF (2 * APL)
#define BUFSZ (2 * APL + 2 * BPL)      /* 37888 */
#define GEMM_SMEM (2 * BUFSZ)          /* 75776 */

__device__ __forceinline__ uint32_t smem_u32(const void* p) {
    uint32_t a;
    asm("{ .reg .u64 t; cvta.to.shared.u64 t, %1; cvt.u32.u64 %0, t; }" : "=r"(a) : "l"(p));
    return a;
}
__device__ __forceinline__ void ldm_x4(uint32_t* r, uint32_t addr) {
    asm volatile("ldmatrix.sync.aligned.m8n8.x4.shared.b16 {%0,%1,%2,%3}, [%4];"
                 : "=r"(r[0]), "=r"(r[1]), "=r"(r[2]), "=r"(r[3]) : "r"(addr));
}
__device__ __forceinline__ void ldm_x4t(uint32_t* r, uint32_t addr) {
    asm volatile("ldmatrix.sync.aligned.m8n8.x4.trans.shared.b16 {%0,%1,%2,%3}, [%4];"
                 : "=r"(r[0]), "=r"(r[1]), "=r"(r[2]), "=r"(r[3]) : "r"(addr));
}

// packed converts: first src operand -> UPPER half (PTX cvt two-operand form)
__device__ __forceinline__ uint32_t bf2(float up, float lo) {
    uint32_t r;
    asm("cvt.rn.bf16x2.f32 %0, %1, %2;" : "=r"(r) : "f"(up), "f"(lo));
    return r;
}
__device__ __forceinline__ uint32_t hf2(float up, float lo) {
    uint32_t r;
    asm("cvt.rn.f16x2.f32 %0, %1, %2;" : "=r"(r) : "f"(up), "f"(lo));
    return r;
}

// fp32 -> (hi, mid) bf16 planes packed as uint2 (4 lanes), packed-cvt version
__device__ __forceinline__ void split2_pack(float4 v, uint2& hw, uint2& mw) {
    hw.x = bf2(v.y, v.x);
    hw.y = bf2(v.w, v.z);
    float h0 = __uint_as_float(hw.x << 16);
    float h1 = __uint_as_float(hw.x & 0xFFFF0000u);
    float h2 = __uint_as_float(hw.y << 16);
    float h3 = __uint_as_float(hw.y & 0xFFFF0000u);
    mw.x = bf2(v.y - h1, v.x - h0);
    mw.y = bf2(v.w - h3, v.z - h2);
}
// fp32 -> f16 single plane
__device__ __forceinline__ uint2 f16_pack(float4 v) {
    uint2 w;
    w.x = hf2(v.y, v.x);
    w.y = hf2(v.w, v.z);
    return w;
}

#define MMA_BF(AF, BF, mi, ni)                                                 \
    asm volatile(                                                              \
        "mma.sync.aligned.m16n8k16.row.col.f32.bf16.bf16.f32 "                 \
        "{%0,%1,%2,%3}, {%4,%5,%6,%7}, {%8,%9}, {%0,%1,%2,%3};"                \
        : "+f"(acc[mi][ni][0]), "+f"(acc[mi][ni][1]),                          \
          "+f"(acc[mi][ni][2]), "+f"(acc[mi][ni][3])                           \
        : "r"(AF[mi][0]), "r"(AF[mi][1]), "r"(AF[mi][2]), "r"(AF[mi][3]),      \
          "r"(BF[ni][0]), "r"(BF[ni][1]))
#define MMA_F16(AF, BF, mi, ni)                                                \
    asm volatile(                                                              \
        "mma.sync.aligned.m16n8k16.row.col.f32.f16.f16.f32 "                   \
        "{%0,%1,%2,%3}, {%4,%5,%6,%7}, {%8,%9}, {%0,%1,%2,%3};"                \
        : "+f"(acc[mi][ni][0]), "+f"(acc[mi][ni][1]),                          \
          "+f"(acc[mi][ni][2]), "+f"(acc[mi][ni][3])                           \
        : "r"(AF[mi][0]), "r"(AF[mi][1]), "r"(AF[mi][2]), "r"(AF[mi][3]),      \
          "r"(BF[ni][0]), "r"(BF[ni][1]))

// ---------------- mixed-precision mma.sync GEMM: C = A @ W ----------------
// BM=128 BN=128 BK=32, 256 threads (8 warps 2x4), warp tile 64x32.
// z (= blockIdx.z + zBase): z<64 qproj (bf16x3); z<128 kproj (bf16x3);
// z>=128: vsum split-K (f16x1).  [r10 ordering, split across two launches]
__global__ __launch_bounds__(256) void gemm_mma(
    const float* __restrict__ q, const float* __restrict__ k,
    const float* __restrict__ v, const float* __restrict__ Wq,
    const float* __restrict__ Wk, const float* __restrict__ Wv,
    int zBase)
{
    extern __shared__ char smc[];
    uint32_t sb = smem_u32(smc);
    int tid = threadIdx.x, lane = tid & 31, warp = tid >> 5;
    int z = blockIdx.z + zBase;
    long bm = (long)blockIdx.y * 128;
    int n0 = blockIdx.x * 128;

    const float* A; const float* W; float* C;
    long lda, ldc; int nChunks; bool np3;
    if (z < 64) {
        A = q + (long)z * 512; W = Wq + (long)z * 262144;
        C = g_qp + (long)z * 512; lda = 32768; ldc = 32768; nChunks = 16; np3 = true;
    } else if (z < 128) {
        int g = z - 64;
        A = k + (long)g * 512; W = Wk + (long)g * 262144;
        C = g_kp + (long)g * 512; lda = 32768; ldc = 32768; nChunks = 16; np3 = true;
    } else {
        int kz = z - 128;
        A = v + (long)kz * 1024;
        W = Wv + (long)kz * 1024 * 512;
        C = g_vpart + (long)kz * VSUM_ELEMS;
        lda = 32768; ldc = 512; nChunks = 32; np3 = false;
    }

    int wm0 = (warp >> 2) * 64;
    int wn0 = (warp & 3) * 32;
    int g8 = lane >> 2, tq = lane & 3;

    int lrow = ((lane >> 3) & 1) * 8 + (lane & 7);
    int lk16 = ((lane >> 4) & 1) * 16;
    uint32_t aLane = sb + AOFF + (uint32_t)(wm0 + lrow) * APITCH_B + lk16;
    uint32_t bLane = sb + BOFF + (uint32_t)lrow * BPITCH_B + (uint32_t)(wn0 + ((lane >> 4) & 1) * 8) * 2;

    int am = tid >> 3, akf = (tid & 7) * 4;
    const float* Aload = A + (bm + am) * lda + akf;

    float acc[4][4][4];
#pragma unroll
    for (int mi = 0; mi < 4; mi++)
#pragma unroll
        for (int ni = 0; ni < 4; ni++)
#pragma unroll
            for (int c = 0; c < 4; c++) acc[mi][ni][c] = 0.f;

    float4 ra[4], rb[4];

#define LOADG(kb)                                                              \
    do {                                                                       \
        _Pragma("unroll")                                                      \
        for (int i = 0; i < 4; i++) {                                          \
            ra[i] = *(const float4*)(Aload + (long)(i * 32) * lda + (kb));     \
            int lin = tid + i * 256;                                           \
            int kk = lin >> 5, nf = lin & 31;                                  \
            rb[i] = *(const float4*)(W + ((kb) + kk) * 512 + n0 + nf * 4);     \
        }                                                                      \
    } while (0)

#define STORE(buf)                                                             \
    do {                                                                       \
        char* bp = smc + (buf) * BUFSZ;                                        \
        _Pragma("unroll")                                                      \
        for (int i = 0; i < 4; i++) {                                          \
            char* ap = bp + AOFF + (am + i * 32) * APITCH_B + akf * 2;         \
            int lin = tid + i * 256;                                           \
            int kk = lin >> 5, nf = lin & 31;                                  \
            char* wp = bp + BOFF + kk * BPITCH_B + nf * 8;                     \
            if (np3) {                                                         \
                uint2 hw, mw;                                                  \
                split2_pack(ra[i], hw, mw);                                    \
                *(uint2*)ap = hw; *(uint2*)(ap + APL) = mw;                    \
                split2_pack(rb[i], hw, mw);                                    \
                *(uint2*)wp = hw; *(uint2*)(wp + BPL) = mw;                    \
            } else {                                                           \
                *(uint2*)ap = f16_pack(ra[i]);                                 \
                *(uint2*)wp = f16_pack(rb[i]);                                 \
            }                                                                  \
        }                                                                      \
    } while (0)

    LOADG(0);
    STORE(0);
    if (nChunks > 1) LOADG(32);
    __syncthreads();

    for (int kt = 0; kt < nChunks; kt++) {
        int cur = kt & 1;
        if (kt + 1 < nChunks) {
            STORE(cur ^ 1);
            if (kt + 2 < nChunks) LOADG((long)(kt + 2) * 32);
        }
        uint32_t bufOff = (uint32_t)cur * BUFSZ;
#pragma unroll
        for (int ks = 0; ks < 2; ks++) {
            uint32_t Ah[4][4], Am[4][4];
#pragma unroll
            for (int mt = 0; mt < 4; mt++) {
                uint32_t ad = aLane + bufOff + mt * (16 * APITCH_B) + ks * 32;
                ldm_x4(Ah[mt], ad);
                if (np3) ldm_x4(Am[mt], ad + APL);
            }
            uint32_t Bh[4][2], Bm[4][2];
#pragma unroll
            for (int pr = 0; pr < 2; pr++) {
                uint32_t bd = bLane + bufOff + ks * (16 * BPITCH_B) + pr * 32;
                uint32_t r4[4];
                ldm_x4t(r4, bd);
                Bh[2 * pr][0] = r4[0]; Bh[2 * pr][1] = r4[1];
                Bh[2 * pr + 1][0] = r4[2]; Bh[2 * pr + 1][1] = r4[3];
                if (np3) {
                    ldm_x4t(r4, bd + BPL);
                    Bm[2 * pr][0] = r4[0]; Bm[2 * pr][1] = r4[1];
                    Bm[2 * pr + 1][0] = r4[2]; Bm[2 * pr + 1][1] = r4[3];
                }
            }
            if (np3) {
#pragma unroll
                for (int mt = 0; mt < 4; mt++)
#pragma unroll
                    for (int nt = 0; nt < 4; nt++) {
                        MMA_BF(Am, Bh, mt, nt);
                        MMA_BF(Ah, Bm, mt, nt);
                        MMA_BF(Ah, Bh, mt, nt);
                    }
            } else {
#pragma unroll
                for (int mt = 0; mt < 4; mt++)
#pragma unroll
                    for (int nt = 0; nt < 4; nt++)
                        MMA_F16(Ah, Bh, mt, nt);
            }
        }
        __syncthreads();
    }
#undef LOADG
#undef STORE

#pragma unroll
    for (int mt = 0; mt < 4; mt++) {
        long r0 = bm + wm0 + mt * 16 + g8;
#pragma unroll
        for (int nt = 0; nt < 4; nt++) {
            long c0 = n0 + wn0 + nt * 8 + 2 * tq;
            *(float2*)(C + r0 * ldc + c0) = make_float2(acc[mt][nt][0], acc[mt][nt][1]);
            *(float2*)(C + (r0 + 8) * ldc + c0) = make_float2(acc[mt][nt][2], acc[mt][nt][3]);
        }
    }
}

// ---------------- split-K reduction for vsum (float2, 256 blocks) ----------------
__global__ __launch_bounds__(256) void reduce_vsum()
{
    int idx = (blockIdx.x * 256 + threadIdx.x) * 2;
    float2 s = make_float2(0.f, 0.f);
#pragma unroll
    for (int i = 0; i < VSPLIT; i++) {
        float2 p = *(const float2*)&g_vpart[(long)i * VSUM_ELEMS + idx];
        s.x += p.x; s.y += p.y;
    }
    *(float2*)&g_vsum[idx] = s;
}

// ---------------- attention weights (MMA-based scores) ----------------
__global__ __launch_bounds__(256) void attn_kernel()
{
    __shared__ __align__(16) unsigned short Qh[64 * 72], Qm[64 * 72];
    __shared__ __align__(16) unsigned short Kh[64 * 72], Km[64 * 72];
    __shared__ float colmax[2][64];
    __shared__ float ev[64], av[64], wv[64];
    __shared__ float red[2], red2[2];
    __shared__ int cntS[4][64];
    __shared__ float dsh;
    int h = blockIdx.x, b = blockIdx.y;
    int t = threadIdx.x, lane = t & 31, w = t >> 5;

    const float* qpB = g_qp + (long)b * 64 * 512 + h * 64;
    const float* kpB = g_kp + (long)b * 64 * 512 + h * 64;
#pragma unroll
    for (int i = 0; i < 4; i++) {
        int idx = t + i * 256;
        int r = idx >> 4, c4 = (idx & 15) * 4;
        float4 qv = *(const float4*)(qpB + (long)r * 512 + c4);
        float4 kv = *(const float4*)(kpB + (long)r * 512 + c4);
        uint2 hw, mw;
        split2_pack(qv, hw, mw);
        *(uint2*)&Qh[r * 72 + c4] = hw;
        *(uint2*)&Qm[r * 72 + c4] = mw;
        split2_pack(kv, hw, mw);
        *(uint2*)&Kh[r * 72 + c4] = hw;
        *(uint2*)&Km[r * 72 + c4] = mw;
    }
    __syncthreads();

    int wr = w & 3, wc = w >> 2;
    int r0 = wr * 16, n0 = wc * 32;
    int am_row = r0 + ((lane >> 3) & 1) * 8 + (lane & 7);
    int am_col = (lane >> 4) * 16;
    uint32_t aQh = smem_u32(Qh) + am_row * 144 + am_col;
    uint32_t aQm = smem_u32(Qm) + am_row * 144 + am_col;
    int sel = (lane >> 3) & 3;
    int brow = (sel >> 1) * 8 + (lane & 7);
    int bcol = (sel & 1) * 16;
    uint32_t aKh = smem_u32(Kh) + bcol;
    uint32_t aKm = smem_u32(Km) + bcol;

    float acc[4][4];
#pragma unroll
    for (int i = 0; i < 4; i++)
#pragma unroll
        for (int j = 0; j < 4; j++) acc[i][j] = 0.f;

#pragma unroll
    for (int ks = 0; ks < 4; ks++) {
        uint32_t Ah[4], Am[4];
        ldm_x4(Ah, aQh + ks * 32);
        ldm_x4(Am, aQm + ks * 32);
#pragma unroll
        for (int ntp = 0; ntp < 2; ntp++) {
            uint32_t off = (uint32_t)(n0 + ntp * 16 + brow) * 144 + ks * 32;
            uint32_t r4[4];
            uint32_t Bh[2][2], Bm[2][2];
            ldm_x4(r4, aKh + off);
            Bh[0][0] = r4[0]; Bh[0][1] = r4[1]; Bh[1][0] = r4[2]; Bh[1][1] = r4[3];
            ldm_x4(r4, aKm + off);
            Bm[0][0] = r4[0]; Bm[0][1] = r4[1]; Bm[1][0] = r4[2]; Bm[1][1] = r4[3];
#pragma unroll
            for (int j = 0; j < 2; j++) {
                int nt = ntp * 2 + j;
                asm volatile(
                    "mma.sync.aligned.m16n8k16.row.col.f32.bf16.bf16.f32 "
                    "{%0,%1,%2,%3}, {%4,%5,%6,%7}, {%8,%9}, {%0,%1,%2,%3};"
                    : "+f"(acc[nt][0]), "+f"(acc[nt][1]), "+f"(acc[nt][2]), "+f"(acc[nt][3])
                    : "r"(Am[0]), "r"(Am[1]), "r"(Am[2]), "r"(Am[3]),
                      "r"(Bh[j][0]), "r"(Bh[j][1]));
                asm volatile(
                    "mma.sync.aligned.m16n8k16.row.col.f32.bf16.bf16.f32 "
                    "{%0,%1,%2,%3}, {%4,%5,%6,%7}, {%8,%9}, {%0,%1,%2,%3};"
                    : "+f"(acc[nt][0]), "+f"(acc[nt][1]), "+f"(acc[nt][2]), "+f"(acc[nt][3])
                    : "r"(Ah[0]), "r"(Ah[1]), "r"(Ah[2]), "r"(Ah[3]),
                      "r"(Bm[j][0]), "r"(Bm[j][1]));
                asm volatile(
                    "mma.sync.aligned.m16n8k16.row.col.f32.bf16.bf16.f32 "
                    "{%0,%1,%2,%3}, {%4,%5,%6,%7}, {%8,%9}, {%0,%1,%2,%3};"
                    : "+f"(acc[nt][0]), "+f"(acc[nt][1]), "+f"(acc[nt][2]), "+f"(acc[nt][3])
                    : "r"(Ah[0]), "r"(Ah[1]), "r"(Ah[2]), "r"(Ah[3]),
                      "r"(Bh[j][0]), "r"(Bh[j][1]));
            }
        }
    }

    float m1 = acc[0][0], m2 = acc[0][2];
#pragma unroll
    for (int nt = 0; nt < 4; nt++) {
        m1 = fmaxf(m1, fmaxf(acc[nt][0], acc[nt][1]));
        m2 = fmaxf(m2, fmaxf(acc[nt][2], acc[nt][3]));
    }
    m1 = fmaxf(m1, __shfl_xor_sync(0xffffffffu, m1, 1));
    m1 = fmaxf(m1, __shfl_xor_sync(0xffffffffu, m1, 2));
    m2 = fmaxf(m2, __shfl_xor_sync(0xffffffffu, m2, 1));
    m2 = fmaxf(m2, __shfl_xor_sync(0xffffffffu, m2, 2));
    if ((lane & 3) == 0) {
        colmax[wc][r0 + (lane >> 2)] = m1;
        colmax[wc][r0 + (lane >> 2) + 8] = m2;
    }
    __syncthreads();
    if (t < 64) ev[t] = expf(fmaxf(colmax[0][t], colmax[1][t]) * 0.125f);
    __syncthreads();

    if (t < 64) {
        float m = ev[t];
#pragma unroll
        for (int s = 16; s > 0; s >>= 1) m = fmaxf(m, __shfl_xor_sync(0xffffffffu, m, s));
        if (lane == 0) red[w] = m;
    }
    __syncthreads();
    if (t < 64) {
        float m = fmaxf(red[0], red[1]);
        float sx = expf(ev[t] - m);
        av[t] = sx;
        float ss = sx;
#pragma unroll
        for (int s = 16; s > 0; s >>= 1) ss += __shfl_xor_sync(0xffffffffu, ss, s);
        if (lane == 0) red2[w] = ss;
    }
    __syncthreads();
    if (t < 64) av[t] = av[t] / (red2[0] + red2[1]);
    __syncthreads();

    {
        int r = t & 63, part = t >> 6;
        float ar = av[r];
        int cnt = 0;
        int j0 = part * 16;
#pragma unroll
        for (int j = 0; j < 16; j++) {
            float o = av[j0 + j];
            cnt += (o > ar) || (o == ar && (j0 + j) < r);
        }
        cntS[part][r] = cnt;
    }
    __syncthreads();
    if (t < 64) {
        int cnt = cntS[0][t] + cntS[1][t] + cntS[2][t] + cntS[3][t];
        if (cnt == TOPKK - 1) dsh = av[t];
    }
    __syncthreads();
    if (t < 64) {
        float wq = fmaxf(av[t] - (dsh + EPSF), 0.f);
        wv[t] = wq;
        float ws = wq;
#pragma unroll
        for (int s = 16; s > 0; s >>= 1) ws += __shfl_xor_sync(0xffffffffu, ws, s);
        if (lane == 0) red[w] = ws;
    }
    __syncthreads();
    if (t < 64)
        g_attn[((long)b * 64 + t) * 8 + h] = wv[t] / (red[0] + red[1] + EPSF);
}

// ---------------- F/G via f16 mma ----------------
#define FG_AP 144
#define FG_BP 144
__global__ __launch_bounds__(256) void fg_mma(const float* __restrict__ fc_w,
                                              const float* __restrict__ gate_w)
{
    __shared__ __align__(16) char As[128 * FG_AP];
    __shared__ __align__(16) char Bs[128 * FG_BP];
    int h = blockIdx.x;
    int b0 = blockIdx.y * 128;
    int zn = blockIdx.z;
    const float* Wsel = (zn < 4) ? fc_w : gate_w;
    float* Out = (zn < 4) ? g_F : g_G;
    int o0 = (zn & 3) * 128;
    int tid = threadIdx.x, lane = tid & 31, warp = tid >> 5;

#pragma unroll
    for (int i = 0; i < 8; i++) {
        int lin = tid + i * 256;
        int r = lin >> 4, c4 = (lin & 15) * 4;
        float4 av = *(const float4*)&g_vsum[(long)(b0 + r) * 512 + h * 64 + c4];
        *(uint2*)(As + r * FG_AP + c4 * 2) = f16_pack(av);
        float4 bv = *(const float4*)&Wsel[(long)(o0 + r) * 512 + h * 64 + c4];
        *(uint2*)(Bs + r * FG_BP + c4 * 2) = f16_pack(bv);
    }
    __syncthreads();

    int wm0 = (warp >> 2) * 64, wn0 = (warp & 3) * 32;
    int g8 = lane >> 2, tq = lane & 3;
    int arow = ((lane >> 3) & 1) * 8 + (lane & 7);
    int acol = (lane >> 4) * 16;
    uint32_t aBase = smem_u32(As) + (uint32_t)(wm0 + arow) * FG_AP + acol;
    int sel = (lane >> 3) & 3;
    int brow = (sel >> 1) * 8 + (lane & 7);
    int bcol = (sel & 1) * 16;
    uint32_t bBase = smem_u32(Bs) + bcol;

    float acc[4][4][4];
#pragma unroll
    for (int mi = 0; mi < 4; mi++)
#pragma unroll
        for (int ni = 0; ni < 4; ni++)
#pragma unroll
            for (int c = 0; c < 4; c++) acc[mi][ni][c] = 0.f;

#pragma unroll
    for (int ks = 0; ks < 4; ks++) {
        uint32_t Af[4][4];
#pragma unroll
        for (int mt = 0; mt < 4; mt++)
            ldm_x4(Af[mt], aBase + mt * (16 * FG_AP) + ks * 32);
        uint32_t Bf[4][2];
#pragma unroll
        for (int ntp = 0; ntp < 2; ntp++) {
            uint32_t r4[4];
            ldm_x4(r4, bBase + (uint32_t)(wn0 + ntp * 16 + brow) * FG_BP + ks * 32);
            Bf[2 * ntp][0] = r4[0]; Bf[2 * ntp][1] = r4[1];
            Bf[2 * ntp + 1][0] = r4[2]; Bf[2 * ntp + 1][1] = r4[3];
        }
#pragma unroll
        for (int mt = 0; mt < 4; mt++)
#pragma unroll
            for (int nt = 0; nt < 4; nt++)
                MMA_F16(Af, Bf, mt, nt);
    }

#pragma unroll
    for (int mt = 0; mt < 4; mt++) {
        int br = b0 + wm0 + mt * 16 + g8;
#pragma unroll
        for (int nt = 0; nt < 4; nt++) {
            int col = o0 + wn0 + nt * 8 + 2 * tq;
            *(float2*)&Out[((long)br * 8 + h) * 512 + col] =
                make_float2(acc[mt][nt][0], acc[mt][nt][1]);
            *(float2*)&Out[((long)(br + 8) * 8 + h) * 512 + col] =
                make_float2(acc[mt][nt][2], acc[mt][nt][3]);
        }
    }
}

// ---------------- final gated combine ----------------
__global__ __launch_bounds__(256) void final_kernel(const float* __restrict__ fc_b,
                                                    const float* __restrict__ gate_b,
                                                    float* __restrict__ out)
{
    __shared__ float aw[64][8];
    __shared__ float Fs[8][128];
    __shared__ float Gs[8][128];
    __shared__ float fb[128], gb[128];
    int o0 = blockIdx.x * 128;
    int b = blockIdx.y;
    int t = threadIdx.x;

    for (int i = t; i < 512; i += 256)
        ((float*)aw)[i] = g_attn[(long)b * 512 + i];
    for (int i = t; i < 1024; i += 256) {
        int h = i >> 7, o = i & 127;
        Fs[h][o] = g_F[((long)b * 8 + h) * 512 + o0 + o];
        Gs[h][o] = g_G[((long)b * 8 + h) * 512 + o0 + o];
    }
    if (t < 128) {
        fb[t] = fc_b[o0 + t];
        gb[t] = gate_b[o0 + t];
    }
    __syncthreads();

    int oc = t & 31, rw = t >> 5;
    for (int r = rw; r < 64; r += 8) {
        float ah[8];
#pragma unroll
        for (int h = 0; h < 8; h++) ah[h] = aw[r][h];
        for (int ob = 0; ob < 128; ob += 32) {
            int o = ob + oc;
            float f = fb[o], g = gb[o];
#pragma unroll
            for (int h = 0; h < 8; h++) {
                f = fmaf(ah[h], Fs[h][o], f);
                g = fmaf(ah[h], Gs[h][o], g);
            }
            float sg = 1.f / (1.f + expf(-g));
            out[((long)b * 64 + r) * 512 + o0 + o] = sg * tanhf(f);
        }
    }
}

// ---------------- launch: fork vsum chain onto a side stream ----------------
extern "C" void kernel_launch(void* const* d_in, const int* in_sizes, int n_in,
                              void* d_out, int out_size)
{
    const float* q      = (const float*)d_in[0];
    const float* k      = (const float*)d_in[1];
    const float* v      = (const float*)d_in[2];
    const float* Wq     = (const float*)d_in[3];
    const float* Wk     = (const float*)d_in[4];
    const float* Wv     = (const float*)d_in[5];
    const float* fc_w   = (const float*)d_in[6];
    const float* fc_b   = (const float*)d_in[7];
    const float* gate_w = (const float*)d_in[8];
    const float* gate_b = (const float*)d_in[9];
    float* out = (float*)d_out;
    (void)in_sizes; (void)n_in; (void)out_size;

    static cudaStream_t s2 = nullptr;
    static cudaEvent_t eFork = nullptr, eJoin = nullptr;
    if (!s2) {
        cudaStreamCreateWithFlags(&s2, cudaStreamNonBlocking);
        cudaEventCreateWithFlags(&eFork, cudaEventDisableTiming);
        cudaEventCreateWithFlags(&eJoin, cudaEventDisableTiming);
        cudaFuncSetAttribute(gemm_mma, cudaFuncAttributeMaxDynamicSharedMemorySize,
                             GEMM_SMEM);
    }

    // fork: side stream runs vsum GEMM -> reduce -> fg while main runs qk GEMM -> attn
    cudaEventRecord(eFork, 0);
    cudaStreamWaitEvent(s2, eFork, 0);

    // side stream: vsum split-K (z 128..159 via zBase=128), reduce, fg
    gemm_mma<<<dim3(4, 2, 32), 256, GEMM_SMEM, s2>>>(q, k, v, Wq, Wk, Wv, 128);
    reduce_vsum<<<VSUM_ELEMS / 512, 256, 0, s2>>>();
    fg_mma<<<dim3(NH, 2, 8), 256, 0, s2>>>(fc_w, gate_w);
    cudaEventRecord(eJoin, s2);

    // main stream: qproj+kproj (z 0..127), then attn
    gemm_mma<<<dim3(4, 2, 128), 256, GEMM_SMEM>>>(q, k, v, Wq, Wk, Wv, 0);
    attn_kernel<<<dim3(NH, Bb), 256>>>();

    // join, then final combine
    cudaStreamWaitEvent(0, eJoin, 0);
    final_kernel<<<dim3(4, Bb), 256>>>(fc_b, gate_b, out);
}